// round 5
// baseline (speedup 1.0000x reference)
#include <cuda_runtime.h>
#include <cstdint>

// GatherBlock: out[m, :, :, :] = x[b[m], :, yb[m]*16 : yb[m]*16+16, xb[m]*16 : xb[m]*16+16]
// x: (8, 64, 256, 256) fp32, indices: (1024, 3) int32, out: (1024, 64, 16, 16) fp32.
//
// R5: same L2-residency plan as R4, fixed for sm_103 ptxas: .L2::evict_last
// requires 256-bit loads, so read with ld.global.nc.L2::evict_last.v8.b32
// (32B per load, tile rows are 64B-aligned so two loads per row). Stores stay
// evict-first (__stcs) so the write stream is the eviction victim and x's
// ~50 MiB unique-tile set persists in the ~126MB L2 across graph replays.

static constexpr int C = 64;
static constexpr int H = 256;
static constexpr int W = 256;
static constexpr int BH = 16;
static constexpr int BW = 16;
static constexpr int CHW = C * H * W;      // 4194304
static constexpr int HW = H * W;           // 65536
static constexpr int OCT_PER_M = C * BH * BW / 8;     // 2048 8-float groups per block
static constexpr int SPLIT = 4;                       // CTAs per m
static constexpr int OCT_PER_CTA = OCT_PER_M / SPLIT; // 512 per CTA

__device__ __forceinline__ void ldg256_evict_last(const float* p, float4& a, float4& b)
{
    unsigned r0, r1, r2, r3, r4, r5, r6, r7;
    asm volatile("ld.global.nc.L2::evict_last.v8.b32 {%0,%1,%2,%3,%4,%5,%6,%7}, [%8];"
                 : "=r"(r0), "=r"(r1), "=r"(r2), "=r"(r3),
                   "=r"(r4), "=r"(r5), "=r"(r6), "=r"(r7)
                 : "l"(p));
    a.x = __uint_as_float(r0); a.y = __uint_as_float(r1);
    a.z = __uint_as_float(r2); a.w = __uint_as_float(r3);
    b.x = __uint_as_float(r4); b.y = __uint_as_float(r5);
    b.z = __uint_as_float(r6); b.w = __uint_as_float(r7);
}

__global__ __launch_bounds__(256, 8)
void gather_block_kernel(const float* __restrict__ x,
                         const int* __restrict__ idx,
                         float4* __restrict__ out)
{
    const int m = blockIdx.x >> 2;        // which output block
    const int q = blockIdx.x & 3;         // which quarter of it

    const int b  = idx[3 * m + 0];
    const int yb = idx[3 * m + 1];
    const int xb = idx[3 * m + 2];

    // base of the gathered tile: x[b, 0, yb*16, xb*16]
    const float* src = x + (size_t)b * CHW + (size_t)(yb * BH) * W + (size_t)(xb * BW);
    float4* dst = out + (size_t)m * (OCT_PER_M * 2);

    const int t = threadIdx.x;

    // oct index o in [0, 2048): c = o>>5, row i = (o>>1)&15, half j = o&1.
    // Each thread handles 2 octs (64B total), front-batched.
    float4 r[4];
#pragma unroll
    for (int k = 0; k < 2; k++) {
        const int o = q * OCT_PER_CTA + t + k * 256;
        const int c = o >> 5;
        const int i = (o >> 1) & 15;
        const int j = o & 1;
        const float* s = src + (size_t)c * HW + (size_t)i * W + j * 8;
        ldg256_evict_last(s, r[2 * k], r[2 * k + 1]);
    }
#pragma unroll
    for (int k = 0; k < 2; k++) {
        const int o = q * OCT_PER_CTA + t + k * 256;
        __stcs(dst + 2 * o,     r[2 * k]);
        __stcs(dst + 2 * o + 1, r[2 * k + 1]);
    }
}

extern "C" void kernel_launch(void* const* d_in, const int* in_sizes, int n_in,
                              void* d_out, int out_size)
{
    const float* x  = (const float*)d_in[0];
    const int* idx  = (const int*)d_in[1];
    float4* out     = (float4*)d_out;

    const int M = in_sizes[1] / 3;  // 1024
    gather_block_kernel<<<M * SPLIT, 256>>>(x, idx, out);
}

// round 6
// speedup vs baseline: 1.0072x; 1.0072x over previous
#include <cuda_runtime.h>
#include <cstdint>

// GatherBlock: out[m, :, :, :] = x[b[m], :, yb[m]*16 : yb[m]*16+16, xb[m]*16 : xb[m]*16+16]
// x: (8, 64, 256, 256) fp32, indices: (1024, 3) int32, out: (1024, 64, 16, 16) fp32.
//
// R6: schedule gather CTAs in tile-address order. Reads are 64B slivers of
// 1KB DRAM rows (x W-rows); randomly-ordered m's open a row per 64B (DRAM
// ~57% busy = activate/precharge overhead). Sorting m by (b,yb,xb) makes
// concurrent CTAs hit the same open rows ((b,yb) collisions: ~8 tiles/row
// group) and lets duplicate tiles coalesce in L2 in the same window.
// Kernel A: 1-CTA bitonic sort of 1024 keys -> __device__ perm array.
// Kernel B: R3 gather (plain LDG.128, evict-first STG.128), m = perm[bid>>2].

static constexpr int C = 64;
static constexpr int H = 256;
static constexpr int W = 256;
static constexpr int BH = 16;
static constexpr int BW = 16;
static constexpr int CHW = C * H * W;      // 4194304
static constexpr int HW = H * W;           // 65536
static constexpr int VEC_PER_M = C * BH * BW / 4;     // 4096 float4 per output block
static constexpr int SPLIT = 4;                       // CTAs per m
static constexpr int VEC_PER_CTA = VEC_PER_M / SPLIT; // 1024 float4 per CTA
static constexpr int M_MAX = 1024;

__device__ int g_perm[M_MAX];

__global__ __launch_bounds__(M_MAX, 1)
void sort_indices_kernel(const int* __restrict__ idx, int M)
{
    __shared__ int keys[M_MAX];
    const int t = threadIdx.x;

    // key = tile id (b,yb,xb) in high bits, m in low 10 bits (tie-break).
    int k;
    if (t < M) {
        const int b  = idx[3 * t + 0];
        const int yb = idx[3 * t + 1];
        const int xb = idx[3 * t + 2];
        k = ((((b << 4) | yb) << 4 | xb) << 10) | t;
    } else {
        k = 0x7FFFFFFF;  // pad to power of two
    }
    keys[t] = k;
    __syncthreads();

    // bitonic sort, 1024 elements, one thread per element
    for (int size = 2; size <= M_MAX; size <<= 1) {
        for (int stride = size >> 1; stride > 0; stride >>= 1) {
            const int partner = t ^ stride;
            if (partner > t) {
                const bool up = (t & size) == 0;
                const int a = keys[t];
                const int c = keys[partner];
                if ((a > c) == up) {
                    keys[t] = c;
                    keys[partner] = a;
                }
            }
            __syncthreads();
        }
    }

    if (t < M) g_perm[t] = keys[t] & 1023;
}

__global__ __launch_bounds__(256, 8)
void gather_block_kernel(const float* __restrict__ x,
                         const int* __restrict__ idx,
                         float4* __restrict__ out)
{
    const int m = g_perm[blockIdx.x >> 2];  // address-sorted order
    const int q = blockIdx.x & 3;           // which quarter of the block

    const int b  = idx[3 * m + 0];
    const int yb = idx[3 * m + 1];
    const int xb = idx[3 * m + 2];

    // base of the gathered tile: x[b, 0, yb*16, xb*16]
    const float* src = x + (size_t)b * CHW + (size_t)(yb * BH) * W + (size_t)(xb * BW);
    float4* dst = out + (size_t)m * VEC_PER_M;

    const int t = threadIdx.x;
    const int v0 = q * VEC_PER_CTA + t;     // starting float4 index within the block

    // v in [0, 4096): c = v>>6, row i = (v>>2)&15, j-vector = v&3.
    float4 r[4];
#pragma unroll
    for (int k = 0; k < 4; k++) {
        const int v = v0 + k * 256;
        const int c = v >> 6;
        const int i = (v >> 2) & 15;
        const int j = v & 3;
        const float4* s = reinterpret_cast<const float4*>(
            src + (size_t)c * HW + (size_t)i * W) + j;
        r[k] = *s;
    }
#pragma unroll
    for (int k = 0; k < 4; k++) {
        __stcs(dst + v0 + k * 256, r[k]);
    }
}

extern "C" void kernel_launch(void* const* d_in, const int* in_sizes, int n_in,
                              void* d_out, int out_size)
{
    const float* x  = (const float*)d_in[0];
    const int* idx  = (const int*)d_in[1];
    float4* out     = (float4*)d_out;

    const int M = in_sizes[1] / 3;  // 1024
    sort_indices_kernel<<<1, M_MAX>>>(idx, M);
    gather_block_kernel<<<M * SPLIT, 256>>>(x, idx, out);
}

// round 7
// speedup vs baseline: 1.1592x; 1.1509x over previous
#include <cuda_runtime.h>
#include <cstdint>

// GatherBlock: out[m, :, :, :] = x[b[m], :, yb[m]*16 : yb[m]*16+16, xb[m]*16 : xb[m]*16+16]
// x: (8, 64, 256, 256) fp32, indices: (1024, 3) int32, out: (1024, 64, 16, 16) fp32.
//
// R7: keep the tile-address-sorted CTA schedule (R6: gather 23.6 -> 22.3 us)
// but replace the 9us bitonic sort with a ~1us counting sort over the 11-bit
// tile id: smem histogram (atomics) -> shfl warp-scan exclusive prefix (4
// barriers total) -> scatter via smem atomicAdd. Gather kernel unchanged:
// SPLIT=4, front-batched LDG.128 (MLP_p1=4), evict-first STG.128 stores.

static constexpr int C = 64;
static constexpr int H = 256;
static constexpr int W = 256;
static constexpr int BH = 16;
static constexpr int BW = 16;
static constexpr int CHW = C * H * W;      // 4194304
static constexpr int HW = H * W;           // 65536
static constexpr int VEC_PER_M = C * BH * BW / 4;     // 4096 float4 per output block
static constexpr int SPLIT = 4;                       // CTAs per m
static constexpr int VEC_PER_CTA = VEC_PER_M / SPLIT; // 1024 float4 per CTA
static constexpr int M_MAX = 1024;
static constexpr int BINS = 2048;                     // 8*16*16 tile ids

__device__ int g_perm[M_MAX];

__global__ __launch_bounds__(M_MAX, 1)
void sort_indices_kernel(const int* __restrict__ idx, int M)
{
    __shared__ unsigned hist[BINS];
    __shared__ unsigned warpsum[32];

    const int t = threadIdx.x;
    const int lane = t & 31;
    const int wid = t >> 5;

    // zero histogram (2 bins per thread)
    hist[2 * t]     = 0;
    hist[2 * t + 1] = 0;
    __syncthreads();

    // build histogram of tile ids
    int key = 0;
    if (t < M) {
        const int b  = idx[3 * t + 0];
        const int yb = idx[3 * t + 1];
        const int xb = idx[3 * t + 2];
        key = (b << 8) | (yb << 4) | xb;   // 11 bits
        atomicAdd(&hist[key], 1u);
    }
    __syncthreads();

    // exclusive prefix sum over 2048 bins, 2 bins/thread, shfl-based
    const unsigned a = hist[2 * t];
    const unsigned bcnt = hist[2 * t + 1];
    const unsigned s = a + bcnt;

    unsigned incl = s;
#pragma unroll
    for (int d = 1; d < 32; d <<= 1) {
        const unsigned n = __shfl_up_sync(0xFFFFFFFFu, incl, d);
        if (lane >= d) incl += n;
    }
    const unsigned thr_excl = incl - s;
    if (lane == 31) warpsum[wid] = incl;
    __syncthreads();

    if (wid == 0) {
        unsigned v = warpsum[lane];
        unsigned pv = v;
#pragma unroll
        for (int d = 1; d < 32; d <<= 1) {
            const unsigned n = __shfl_up_sync(0xFFFFFFFFu, pv, d);
            if (lane >= d) pv += n;
        }
        warpsum[lane] = pv - v;  // exclusive warp offsets
    }
    __syncthreads();

    const unsigned base = warpsum[wid] + thr_excl;
    hist[2 * t]     = base;          // exclusive offset of bin 2t
    hist[2 * t + 1] = base + a;      // exclusive offset of bin 2t+1
    __syncthreads();

    // scatter: perm is m-values grouped by tile id
    if (t < M) {
        const unsigned pos = atomicAdd(&hist[key], 1u);
        g_perm[pos] = t;
    }
}

__global__ __launch_bounds__(256, 8)
void gather_block_kernel(const float* __restrict__ x,
                         const int* __restrict__ idx,
                         float4* __restrict__ out)
{
    const int m = g_perm[blockIdx.x >> 2];  // address-sorted order
    const int q = blockIdx.x & 3;           // which quarter of the block

    const int b  = idx[3 * m + 0];
    const int yb = idx[3 * m + 1];
    const int xb = idx[3 * m + 2];

    // base of the gathered tile: x[b, 0, yb*16, xb*16]
    const float* src = x + (size_t)b * CHW + (size_t)(yb * BH) * W + (size_t)(xb * BW);
    float4* dst = out + (size_t)m * VEC_PER_M;

    const int t = threadIdx.x;
    const int v0 = q * VEC_PER_CTA + t;     // starting float4 index within the block

    // v in [0, 4096): c = v>>6, row i = (v>>2)&15, j-vector = v&3.
    float4 r[4];
#pragma unroll
    for (int k = 0; k < 4; k++) {
        const int v = v0 + k * 256;
        const int c = v >> 6;
        const int i = (v >> 2) & 15;
        const int j = v & 3;
        const float4* s = reinterpret_cast<const float4*>(
            src + (size_t)c * HW + (size_t)i * W) + j;
        r[k] = *s;
    }
#pragma unroll
    for (int k = 0; k < 4; k++) {
        __stcs(dst + v0 + k * 256, r[k]);
    }
}

extern "C" void kernel_launch(void* const* d_in, const int* in_sizes, int n_in,
                              void* d_out, int out_size)
{
    const float* x  = (const float*)d_in[0];
    const int* idx  = (const int*)d_in[1];
    float4* out     = (float4*)d_out;

    const int M = in_sizes[1] / 3;  // 1024
    sort_indices_kernel<<<1, M_MAX>>>(idx, M);
    gather_block_kernel<<<M * SPLIT, 256>>>(x, idx, out);
}